// round 2
// baseline (speedup 1.0000x reference)
#include <cuda_runtime.h>
#include <stdint.h>

// Problem constants (match reference)
#define BB      1024        // batch
#define PP      512         // patches
#define KK      128         // dim
#define NM      819         // int(B*0.8)
#define NMR     921         // NM + int(B*0.1)
#define MAXC    76          // int(0.15*4096/8)
#define NTOT    67108864    // B*P*K
#define I_OFF   67108864
#define MT_OFF  (67108864 + 1024*76)

// Device globals (no allocation allowed)
__device__ uint32_t g_kr0, g_kr1;
__device__ int g_mode;
__device__ unsigned char g_sel[BB * PP];

// ---------------------------------------------------------------------------
// threefry2x32, exactly as in jax/_src/prng.py (5 groups of 4 rounds)
// ---------------------------------------------------------------------------
__device__ __forceinline__ uint2 tf2x32(uint32_t k0, uint32_t k1,
                                        uint32_t x0, uint32_t x1) {
    uint32_t k2 = k0 ^ k1 ^ 0x1BD11BDAu;
    x0 += k0; x1 += k1;
#define TFR(r) { x0 += x1; x1 = (x1 << (r)) | (x1 >> (32 - (r))); x1 ^= x0; }
    TFR(13) TFR(15) TFR(26) TFR(6)
    x0 += k1; x1 += k2 + 1u;
    TFR(17) TFR(29) TFR(16) TFR(24)
    x0 += k2; x1 += k0 + 2u;
    TFR(13) TFR(15) TFR(26) TFR(6)
    x0 += k0; x1 += k1 + 3u;
    TFR(17) TFR(29) TFR(16) TFR(24)
    x0 += k1; x1 += k2 + 4u;
    TFR(13) TFR(15) TFR(26) TFR(6)
    x0 += k2; x1 += k0 + 5u;
#undef TFR
    return make_uint2(x0, x1);
}

// Partitionable-threefry 32-bit random bits for element index i (i < 2^32):
// counter = (0, i), output = out0 ^ out1.
__device__ __forceinline__ uint32_t rbits32(uint32_t k0, uint32_t k1, uint32_t i) {
    uint2 r = tf2x32(k0, k1, 0u, i);
    return r.x ^ r.y;
}

// ---------------------------------------------------------------------------
// Kernel 1: permutation of 1024 via stable-rank counting, one block per
// element. rank(i) over composite keys (bits<<10 | idx) == position of
// element i in the stable sort, so mask_type[i] = grp(rank(i)).
// Also derives and publishes kr for k_main, and g_mode.
// ---------------------------------------------------------------------------
__global__ void k_perm(float* __restrict__ mt_out) {
    __shared__ uint32_t ssub[2];
    __shared__ int sred[8];
    int i = blockIdx.x;       // element being ranked
    int t = threadIdx.x;      // 256 threads
    if (t == 0) {
        uint2 kp  = tf2x32(0u, 42u, 0u, 0u);      // split(key(42),3)[0]
        uint2 sub = tf2x32(kp.x, kp.y, 0u, 1u);   // _shuffle's subkey
        ssub[0] = sub.x; ssub[1] = sub.y;
        if (i == 0) {
            uint2 kr = tf2x32(0u, 42u, 0u, 2u);   // split(key(42),3)[2]
            g_kr0 = kr.x; g_kr1 = kr.y;
        }
    }
    __syncthreads();
    uint32_t s0 = ssub[0], s1 = ssub[1];
    unsigned long long ki =
        ((unsigned long long)rbits32(s0, s1, (uint32_t)i) << 10) | (unsigned)i;
    int cnt = 0;
#pragma unroll
    for (int r = 0; r < 4; r++) {
        int j = t + (r << 8);
        unsigned long long kj =
            ((unsigned long long)rbits32(s0, s1, (uint32_t)j) << 10) | (unsigned)j;
        cnt += (kj < ki);
    }
    // reduce 256 -> 1
#pragma unroll
    for (int o = 16; o > 0; o >>= 1) cnt += __shfl_down_sync(0xffffffffu, cnt, o);
    if ((t & 31) == 0) sred[t >> 5] = cnt;
    __syncthreads();
    if (t == 0) {
        int rank = sred[0] + sred[1] + sred[2] + sred[3] +
                   sred[4] + sred[5] + sred[6] + sred[7];
        int grp = (rank < NM) ? 0 : ((rank < NMR) ? 1 : 2);
        mt_out[i] = (float)grp;
        if (i == 0) g_mode = grp;
    }
}

// ---------------------------------------------------------------------------
// Kernel 2: per-row stable argsort rank via counting (no sort). One block per
// batch row, 512 threads. Writes sel map + padded I.
// ---------------------------------------------------------------------------
__global__ void k_scores(const int* __restrict__ seq_len, float* __restrict__ I_out) {
    __shared__ unsigned long long sk[PP];
    __shared__ uint32_t sks[2];
    int b = blockIdx.x;
    int p = threadIdx.x;
    if (p == 0) {
        uint2 ks = tf2x32(0u, 42u, 0u, 1u);       // split(key(42),3)[1]
        sks[0] = ks.x; sks[1] = ks.y;
    }
    __syncthreads();
    int sl = seq_len[b];
    int nv = sl >> 3;  // seq_len // PATCH
    // uniform(ks,(B,P)) ordering == ordering of the 23-bit mantissa (bits>>9)
    uint32_t m = rbits32(sks[0], sks[1], (uint32_t)(b * PP + p)) >> 9;
    uint32_t keyhi = (p < nv) ? m : 0x00800000u;  // +inf sentinel > any mantissa
    unsigned long long key = ((unsigned long long)keyhi << 32) | (unsigned)p;
    sk[p] = key;
    __syncthreads();
    int r = 0;
#pragma unroll 8
    for (int j = 0; j < PP; j++) r += (sk[j] < key);   // broadcast shared reads
    // n_corr = floor(0.15f * float(seq_len) / 8.0f), f32 rounding as in JAX
    int nc = (int)floorf(0.15f * (float)sl / 8.0f);
    g_sel[b * PP + p] = (r < nc) ? 1 : 0;
    if (r < nc)            I_out[b * MAXC + r] = (float)p;   // I[b][rank]=patch
    if (p >= nc && p < MAXC) I_out[b * MAXC + p] = -1.0f;    // pad slots
}

// ---------------------------------------------------------------------------
// Kernel 3: main output pass, float4 vectorized, streaming hints. One warp
// covers exactly one patch (K=128), so the sel branch is warp-uniform.
// ---------------------------------------------------------------------------
__global__ void k_main(const float* __restrict__ x, const float* __restrict__ pos,
                       const float* __restrict__ wm, float* __restrict__ out) {
    int t = blockIdx.x * blockDim.x + threadIdx.x;  // 16,777,216 float4 slots
    int e = t << 2;                                  // element index < 2^27
    int mode = g_mode;
    bool s = g_sel[e >> 7] != 0;  // (b*512+p)
    float4 o;
    if (!s || mode == 2) {
        o = __ldcs((const float4*)x + t);            // streaming read
    } else {
        float4 po = *(const float4*)(pos + (e & 65535));  // pos[p*K + k], L2-hot
        if (mode == 0) {
            float4 w = *(const float4*)(wm + (e & 127));
            o = make_float4(w.x + po.x, w.y + po.y, w.z + po.z, w.w + po.w);
        } else {
            uint32_t kr0 = g_kr0, kr1 = g_kr1;
            float u[4];
#pragma unroll
            for (int j = 0; j < 4; j++) {
                uint32_t bits = rbits32(kr0, kr1, (uint32_t)(e + j));
                u[j] = __uint_as_float((bits >> 9) | 0x3f800000u) - 1.0f;
            }
            o = make_float4(u[0] + po.x, u[1] + po.y, u[2] + po.z, u[3] + po.w);
        }
    }
    __stcs((float4*)out + t, o);                     // streaming write
}

// ---------------------------------------------------------------------------
extern "C" void kernel_launch(void* const* d_in, const int* in_sizes, int n_in,
                              void* d_out, int out_size) {
    const float* x   = (const float*)d_in[0];
    const float* pos = (const float*)d_in[1];
    const float* wm  = (const float*)d_in[2];
    const int* sl    = (const int*)d_in[3];
    float* out = (float*)d_out;

    k_perm<<<BB, 256>>>(out + MT_OFF);
    k_scores<<<BB, PP>>>(sl, out + I_OFF);
    k_main<<<NTOT / 4 / 256, 256>>>(x, pos, wm, out);
}

// round 3
// speedup vs baseline: 1.0644x; 1.0644x over previous
#include <cuda_runtime.h>
#include <stdint.h>

// Problem constants (match reference)
#define BB      1024        // batch
#define PP      512         // patches
#define KK      128         // dim
#define NM      819         // int(B*0.8)
#define NMR     921         // NM + int(B*0.1)
#define MAXC    76          // int(0.15*4096/8)
#define NTOT    67108864    // B*P*K
#define I_OFF   67108864
#define MT_OFF  (67108864 + 1024*76)

// Device globals (no allocation allowed)
__device__ uint32_t g_kr0, g_kr1;
__device__ int g_mode;
__device__ unsigned char g_sel[BB * PP];

// ---------------------------------------------------------------------------
// threefry2x32, exactly as in jax/_src/prng.py (5 groups of 4 rounds)
// ---------------------------------------------------------------------------
__device__ __forceinline__ uint2 tf2x32(uint32_t k0, uint32_t k1,
                                        uint32_t x0, uint32_t x1) {
    uint32_t k2 = k0 ^ k1 ^ 0x1BD11BDAu;
    x0 += k0; x1 += k1;
#define TFR(r) { x0 += x1; x1 = (x1 << (r)) | (x1 >> (32 - (r))); x1 ^= x0; }
    TFR(13) TFR(15) TFR(26) TFR(6)
    x0 += k1; x1 += k2 + 1u;
    TFR(17) TFR(29) TFR(16) TFR(24)
    x0 += k2; x1 += k0 + 2u;
    TFR(13) TFR(15) TFR(26) TFR(6)
    x0 += k0; x1 += k1 + 3u;
    TFR(17) TFR(29) TFR(16) TFR(24)
    x0 += k1; x1 += k2 + 4u;
    TFR(13) TFR(15) TFR(26) TFR(6)
    x0 += k2; x1 += k0 + 5u;
#undef TFR
    return make_uint2(x0, x1);
}

// Partitionable-threefry 32-bit random bits for element index i (i < 2^32):
// counter = (0, i), output = out0 ^ out1.
__device__ __forceinline__ uint32_t rbits32(uint32_t k0, uint32_t k1, uint32_t i) {
    uint2 r = tf2x32(k0, k1, 0u, i);
    return r.x ^ r.y;
}

// ---------------------------------------------------------------------------
// Fused setup kernel: 1024 blocks x 512 threads.
//  Part A (scores): per-row stable-argsort rank via counting -> sel map + I.
//  Part B (perm):   block b computes the stable-sort rank of permutation
//                   element b over all 1024 composite keys -> mask_type[b].
// Rank-count is mathematically identical to the stable sorts it replaces:
// rank(i) = #{j : (key_j, j) < (key_i, i)}.
// ---------------------------------------------------------------------------
__global__ void k_setup(const int* __restrict__ seq_len,
                        float* __restrict__ I_out,
                        float* __restrict__ mt_out) {
    __shared__ unsigned long long sk[PP];
    __shared__ uint32_t skey[4];          // ks0, ks1, sub0, sub1
    __shared__ unsigned long long s_ki;   // perm composite key for element b
    __shared__ int s_cnt;
    int b = blockIdx.x;
    int p = threadIdx.x;
    if (p == 0) {
        uint2 kp  = tf2x32(0u, 42u, 0u, 0u);      // split(key(42),3)[0]
        uint2 ks  = tf2x32(0u, 42u, 0u, 1u);      // split(key(42),3)[1]
        uint2 sub = tf2x32(kp.x, kp.y, 0u, 1u);   // _shuffle's subkey
        skey[0] = ks.x;  skey[1] = ks.y;
        skey[2] = sub.x; skey[3] = sub.y;
        s_ki = ((unsigned long long)rbits32(sub.x, sub.y, (uint32_t)b) << 10)
               | (unsigned)b;
        s_cnt = 0;
        if (b == 0) {
            uint2 kr = tf2x32(0u, 42u, 0u, 2u);   // split(key(42),3)[2]
            g_kr0 = kr.x; g_kr1 = kr.y;
        }
    }
    __syncthreads();

    // ---- Part A: row-score key ----
    int sl = seq_len[b];
    int nv = sl >> 3;  // seq_len // PATCH
    // uniform(ks,(B,P)) ordering == ordering of the 23-bit mantissa (bits>>9)
    uint32_t m = rbits32(skey[0], skey[1], (uint32_t)(b * PP + p)) >> 9;
    uint32_t keyhi = (p < nv) ? m : 0x00800000u;  // +inf sentinel > any mantissa
    unsigned long long key = ((unsigned long long)keyhi << 32) | (unsigned)p;
    sk[p] = key;

    // ---- Part B: perm rank contribution (2 elements per thread) ----
    {
        unsigned long long ki = s_ki;
        uint32_t s0 = skey[2], s1 = skey[3];
        int cnt = 0;
#pragma unroll
        for (int rr = 0; rr < 2; rr++) {
            int j = p + (rr << 9);
            unsigned long long kj =
                ((unsigned long long)rbits32(s0, s1, (uint32_t)j) << 10)
                | (unsigned)j;
            cnt += (kj < ki);
        }
#pragma unroll
        for (int o = 16; o > 0; o >>= 1)
            cnt += __shfl_down_sync(0xffffffffu, cnt, o);
        if ((p & 31) == 0 && cnt) atomicAdd(&s_cnt, cnt);
    }
    __syncthreads();

    // ---- Part A: rank count over shared keys (broadcast reads, no syncs) ----
    int r = 0;
#pragma unroll 8
    for (int j = 0; j < PP; j++) r += (sk[j] < key);
    // n_corr = floor(0.15f * float(seq_len) / 8.0f), f32 rounding as in JAX
    int nc = (int)floorf(0.15f * (float)sl / 8.0f);
    g_sel[b * PP + p] = (r < nc) ? 1 : 0;
    if (r < nc)              I_out[b * MAXC + r] = (float)p;   // I[b][rank]=patch
    if (p >= nc && p < MAXC) I_out[b * MAXC + p] = -1.0f;      // pad slots

    // ---- Part B: finalize mask_type[b] ----
    if (p == 0) {
        int rank = s_cnt;
        int grp = (rank < NM) ? 0 : ((rank < NMR) ? 1 : 2);
        mt_out[b] = (float)grp;
        if (b == 0) g_mode = grp;
    }
}

// ---------------------------------------------------------------------------
// Main output pass: 4 independent float4 slots per thread (MLP=4), plain
// cached loads/stores (streaming hints measurably regressed on B300).
// One warp covers exactly one patch (K=128) -> sel branch is warp-uniform.
// ---------------------------------------------------------------------------
__global__ void k_main(const float* __restrict__ x, const float* __restrict__ pos,
                       const float* __restrict__ wm, float* __restrict__ out) {
    int base = (blockIdx.x << 10) + threadIdx.x;   // 1024 float4 per block
    int mode = g_mode;
    // Batch the 4 sel-map loads first (independent, front-loaded MLP)
    unsigned char sv[4];
#pragma unroll
    for (int j = 0; j < 4; j++)
        sv[j] = g_sel[(base + (j << 8)) >> 5];     // (t<<2)>>7 == t>>5
#pragma unroll
    for (int j = 0; j < 4; j++) {
        int t = base + (j << 8);
        int e = t << 2;                            // element index < 2^27
        float4 o;
        if (!sv[j] || mode == 2) {
            o = ((const float4*)x)[t];
        } else {
            float4 po = *(const float4*)(pos + (e & 65535));  // pos[p*K+k], L2-hot
            if (mode == 0) {
                float4 w = *(const float4*)(wm + (e & 127));
                o = make_float4(w.x + po.x, w.y + po.y, w.z + po.z, w.w + po.w);
            } else {
                uint32_t kr0 = g_kr0, kr1 = g_kr1;
                float u[4];
#pragma unroll
                for (int q = 0; q < 4; q++) {
                    uint32_t bits = rbits32(kr0, kr1, (uint32_t)(e + q));
                    u[q] = __uint_as_float((bits >> 9) | 0x3f800000u) - 1.0f;
                }
                o = make_float4(u[0] + po.x, u[1] + po.y, u[2] + po.z, u[3] + po.w);
            }
        }
        ((float4*)out)[t] = o;
    }
}

// ---------------------------------------------------------------------------
extern "C" void kernel_launch(void* const* d_in, const int* in_sizes, int n_in,
                              void* d_out, int out_size) {
    const float* x   = (const float*)d_in[0];
    const float* pos = (const float*)d_in[1];
    const float* wm  = (const float*)d_in[2];
    const int* sl    = (const int*)d_in[3];
    float* out = (float*)d_out;

    k_setup<<<BB, PP>>>(sl, out + I_OFF, out + MT_OFF);
    k_main<<<NTOT / 4 / 1024, 256>>>(x, pos, wm, out);
}

// round 4
// speedup vs baseline: 1.4855x; 1.3956x over previous
#include <cuda_runtime.h>
#include <stdint.h>

// Problem constants (match reference)
#define BB      1024        // batch
#define PP      512         // patches
#define KK      128         // dim
#define NM      819         // int(B*0.8)
#define NMR     921         // NM + int(B*0.1)
#define MAXC    76          // int(0.15*4096/8)
#define NTOT    67108864    // B*P*K
#define I_OFF   67108864
#define MT_OFF  (67108864 + 1024*76)

// Device globals (no allocation allowed)
__device__ uint32_t g_kr0, g_kr1;
__device__ int g_mode;
__device__ unsigned char g_sel[BB * PP];

// ---------------------------------------------------------------------------
// threefry2x32, exactly as in jax/_src/prng.py (5 groups of 4 rounds)
// ---------------------------------------------------------------------------
__device__ __forceinline__ uint2 tf2x32(uint32_t k0, uint32_t k1,
                                        uint32_t x0, uint32_t x1) {
    uint32_t k2 = k0 ^ k1 ^ 0x1BD11BDAu;
    x0 += k0; x1 += k1;
#define TFR(r) { x0 += x1; x1 = (x1 << (r)) | (x1 >> (32 - (r))); x1 ^= x0; }
    TFR(13) TFR(15) TFR(26) TFR(6)
    x0 += k1; x1 += k2 + 1u;
    TFR(17) TFR(29) TFR(16) TFR(24)
    x0 += k2; x1 += k0 + 2u;
    TFR(13) TFR(15) TFR(26) TFR(6)
    x0 += k0; x1 += k1 + 3u;
    TFR(17) TFR(29) TFR(16) TFR(24)
    x0 += k1; x1 += k2 + 4u;
    TFR(13) TFR(15) TFR(26) TFR(6)
    x0 += k2; x1 += k0 + 5u;
#undef TFR
    return make_uint2(x0, x1);
}

// Partitionable-threefry 32-bit random bits for element index i (i < 2^32):
// counter = (0, i), output = out0 ^ out1.
__device__ __forceinline__ uint32_t rbits32(uint32_t k0, uint32_t k1, uint32_t i) {
    uint2 r = tf2x32(k0, k1, 0u, i);
    return r.x ^ r.y;
}

// ---------------------------------------------------------------------------
// Fused setup kernel: 1024 blocks x 512 threads.
//  Part A (scores): per-row stable-argsort rank via EXACT bucket-radix rank:
//    rank(p) = pfx[bucket(p)] + #{q in bucket(p) : key_q < key_p}.
//    Buckets = top 8 bits of the 24-bit keyhi; sentinel bucket 256 for
//    invalid patches (rank there is >= n_valid >= n_corr, never selected).
//    Composite key (keyhi<<32 | p) makes the within-bucket comparison stable
//    regardless of atomic arrival order.
//  Part B (perm): block b computes the stable-sort rank of permutation
//    element b over all 1024 composite keys -> mask_type[b].
// ---------------------------------------------------------------------------
__global__ void k_setup(const int* __restrict__ seq_len,
                        float* __restrict__ I_out,
                        float* __restrict__ mt_out) {
    __shared__ unsigned long long skeys[PP];  // keys grouped by bucket
    __shared__ int hist[257];
    __shared__ int pfx[258];
    __shared__ uint32_t skey[4];              // ks0, ks1, sub0, sub1
    __shared__ unsigned long long s_ki;       // perm composite key for element b
    __shared__ int s_cnt;
    int b = blockIdx.x;
    int p = threadIdx.x;
    if (p == 0) {
        uint2 kp  = tf2x32(0u, 42u, 0u, 0u);      // split(key(42),3)[0]
        uint2 ks  = tf2x32(0u, 42u, 0u, 1u);      // split(key(42),3)[1]
        uint2 sub = tf2x32(kp.x, kp.y, 0u, 1u);   // _shuffle's subkey
        skey[0] = ks.x;  skey[1] = ks.y;
        skey[2] = sub.x; skey[3] = sub.y;
        s_ki = ((unsigned long long)rbits32(sub.x, sub.y, (uint32_t)b) << 10)
               | (unsigned)b;
        s_cnt = 0;
        if (b == 0) {
            uint2 kr = tf2x32(0u, 42u, 0u, 2u);   // split(key(42),3)[2]
            g_kr0 = kr.x; g_kr1 = kr.y;
        }
    }
    if (p < 257) hist[p] = 0;
    __syncthreads();

    // ---- Part A: row-score key + bucket ----
    int sl = seq_len[b];
    int nv = sl >> 3;  // seq_len // PATCH
    // uniform(ks,(B,P)) ordering == ordering of the 23-bit mantissa (bits>>9)
    uint32_t m = rbits32(skey[0], skey[1], (uint32_t)(b * PP + p)) >> 9;
    bool valid = (p < nv);
    uint32_t keyhi = valid ? m : 0x00800000u;  // +inf sentinel > any mantissa
    unsigned long long key = ((unsigned long long)keyhi << 32) | (unsigned)p;
    int bucket = valid ? (int)(keyhi >> 15) : 256;   // 0..255 valid, 256 invalid

    // ---- Part B: perm rank contribution (2 elements per thread) ----
    {
        unsigned long long ki = s_ki;
        uint32_t s0 = skey[2], s1 = skey[3];
        int cnt = 0;
#pragma unroll
        for (int rr = 0; rr < 2; rr++) {
            int j = p + (rr << 9);
            unsigned long long kj =
                ((unsigned long long)rbits32(s0, s1, (uint32_t)j) << 10)
                | (unsigned)j;
            cnt += (kj < ki);
        }
#pragma unroll
        for (int o = 16; o > 0; o >>= 1)
            cnt += __shfl_down_sync(0xffffffffu, cnt, o);
        if ((p & 31) == 0 && cnt) atomicAdd(&s_cnt, cnt);
    }

    // ---- Part A: histogram ----
    int ofs = atomicAdd(&hist[bucket], 1);    // arrival offset within bucket
    __syncthreads();

    // ---- exclusive prefix scan over 257 buckets (warp 0) ----
    if (p < 32) {
        int base = p * 9;                     // 32*9 = 288 >= 258
        int loc[9];
        int s = 0;
#pragma unroll
        for (int i = 0; i < 9; i++) {
            int idx = base + i;
            int v = (idx < 257) ? hist[idx] : 0;
            loc[i] = s; s += v;
        }
        int t = s;
#pragma unroll
        for (int o = 1; o < 32; o <<= 1) {
            int u = __shfl_up_sync(0xffffffffu, t, o);
            if (p >= o) t += u;
        }
        int excl = t - s;                     // exclusive prefix of chunk totals
#pragma unroll
        for (int i = 0; i < 9; i++) {
            int idx = base + i;
            if (idx < 258) pfx[idx] = excl + loc[i];
        }
    }
    __syncthreads();

    // ---- scatter keys into bucket-grouped order ----
    int start = pfx[bucket];
    skeys[start + ofs] = key;
    __syncthreads();

    // ---- exact rank: prefix + within-bucket smaller count ----
    int r;
    if (valid) {
        int end = pfx[bucket + 1];
        r = start;
        for (int j = start; j < end; j++) r += (skeys[j] < key);
    } else {
        r = start;   // start = n_valid >= n_corr -> never selected
    }
    // n_corr = floor(0.15f * float(seq_len) / 8.0f), f32 rounding as in JAX
    int nc = (int)floorf(0.15f * (float)sl / 8.0f);
    g_sel[b * PP + p] = (r < nc) ? 1 : 0;
    if (r < nc)              I_out[b * MAXC + r] = (float)p;   // I[b][rank]=patch
    if (p >= nc && p < MAXC) I_out[b * MAXC + p] = -1.0f;      // pad slots

    // ---- Part B: finalize mask_type[b] ----
    if (p == 0) {
        int rank = s_cnt;
        int grp = (rank < NM) ? 0 : ((rank < NMR) ? 1 : 2);
        mt_out[b] = (float)grp;
        if (b == 0) g_mode = grp;
    }
}

// ---------------------------------------------------------------------------
// Main output pass: 4 independent float4 slots per thread (MLP=4), plain
// cached loads/stores. At the B300 LTS ceiling (~6.25 TB/s) — do not touch.
// Each j-iteration is warp-uniform in sel (one warp spans one patch, K=128).
// ---------------------------------------------------------------------------
__global__ void k_main(const float* __restrict__ x, const float* __restrict__ pos,
                       const float* __restrict__ wm, float* __restrict__ out) {
    int base = (blockIdx.x << 10) + threadIdx.x;   // 1024 float4 per block
    int mode = g_mode;
    unsigned char sv[4];
#pragma unroll
    for (int j = 0; j < 4; j++)
        sv[j] = g_sel[(base + (j << 8)) >> 5];     // (t<<2)>>7 == t>>5
#pragma unroll
    for (int j = 0; j < 4; j++) {
        int t = base + (j << 8);
        int e = t << 2;                            // element index < 2^27
        float4 o;
        if (!sv[j] || mode == 2) {
            o = ((const float4*)x)[t];
        } else {
            float4 po = *(const float4*)(pos + (e & 65535));  // pos[p*K+k], L2-hot
            if (mode == 0) {
                float4 w = *(const float4*)(wm + (e & 127));
                o = make_float4(w.x + po.x, w.y + po.y, w.z + po.z, w.w + po.w);
            } else {
                uint32_t kr0 = g_kr0, kr1 = g_kr1;
                float u[4];
#pragma unroll
                for (int q = 0; q < 4; q++) {
                    uint32_t bits = rbits32(kr0, kr1, (uint32_t)(e + q));
                    u[q] = __uint_as_float((bits >> 9) | 0x3f800000u) - 1.0f;
                }
                o = make_float4(u[0] + po.x, u[1] + po.y, u[2] + po.z, u[3] + po.w);
            }
        }
        ((float4*)out)[t] = o;
    }
}

// ---------------------------------------------------------------------------
extern "C" void kernel_launch(void* const* d_in, const int* in_sizes, int n_in,
                              void* d_out, int out_size) {
    const float* x   = (const float*)d_in[0];
    const float* pos = (const float*)d_in[1];
    const float* wm  = (const float*)d_in[2];
    const int* sl    = (const int*)d_in[3];
    float* out = (float*)d_out;

    k_setup<<<BB, PP>>>(sl, out + I_OFF, out + MT_OFF);
    k_main<<<NTOT / 4 / 1024, 256>>>(x, pos, wm, out);
}

// round 5
// speedup vs baseline: 1.5259x; 1.0272x over previous
#include <cuda_runtime.h>
#include <stdint.h>

// Problem constants (match reference)
#define BB      1024        // batch
#define PP      512         // patches
#define KK      128         // dim
#define NM      819         // int(B*0.8)
#define NMR     921         // NM + int(B*0.1)
#define MAXC    76          // int(0.15*4096/8)
#define NTOT    67108864    // B*P*K
#define I_OFF   67108864
#define MT_OFF  (67108864 + 1024*76)

// Device globals (no allocation allowed)
__device__ uint32_t g_kr0, g_kr1;
__device__ int g_mode;
__device__ unsigned char g_sel[BB * PP];

// ---------------------------------------------------------------------------
// threefry2x32, exactly as in jax/_src/prng.py (5 groups of 4 rounds)
// ---------------------------------------------------------------------------
__device__ __forceinline__ uint2 tf2x32(uint32_t k0, uint32_t k1,
                                        uint32_t x0, uint32_t x1) {
    uint32_t k2 = k0 ^ k1 ^ 0x1BD11BDAu;
    x0 += k0; x1 += k1;
#define TFR(r) { x0 += x1; x1 = (x1 << (r)) | (x1 >> (32 - (r))); x1 ^= x0; }
    TFR(13) TFR(15) TFR(26) TFR(6)
    x0 += k1; x1 += k2 + 1u;
    TFR(17) TFR(29) TFR(16) TFR(24)
    x0 += k2; x1 += k0 + 2u;
    TFR(13) TFR(15) TFR(26) TFR(6)
    x0 += k0; x1 += k1 + 3u;
    TFR(17) TFR(29) TFR(16) TFR(24)
    x0 += k1; x1 += k2 + 4u;
    TFR(13) TFR(15) TFR(26) TFR(6)
    x0 += k2; x1 += k0 + 5u;
#undef TFR
    return make_uint2(x0, x1);
}

// Partitionable-threefry 32-bit random bits for element index i (i < 2^32):
// counter = (0, i), output = out0 ^ out1.
__device__ __forceinline__ uint32_t rbits32(uint32_t k0, uint32_t k1, uint32_t i) {
    uint2 r = tf2x32(k0, k1, 0u, i);
    return r.x ^ r.y;
}

// ---------------------------------------------------------------------------
// Fused setup kernel: 1024 blocks x 512 threads.
//  Part A (all blocks): per-row stable-argsort rank via exact bucket-radix
//    rank -> sel map + I. Threefry is skipped for invalid patches (their key
//    is the +inf sentinel; the hash value is never consumed).
//  Part B (block 0 ONLY): stable-sort rank of ALL 1024 permutation elements
//    via the same bucket-radix trick (2 elems/thread) -> mask_type + g_mode.
// rank(i) = #{j : (key_j, j) < (key_i, i)} == stable-sort position, exactly.
// ---------------------------------------------------------------------------
__global__ void k_setup(const int* __restrict__ seq_len,
                        float* __restrict__ I_out,
                        float* __restrict__ mt_out) {
    __shared__ unsigned long long skeys[PP];    // row keys grouped by bucket
    __shared__ unsigned long long pkeys[2*PP];  // perm keys (block 0 only)
    __shared__ int hist[257];
    __shared__ int pfx[258];
    __shared__ int hist2[256];
    __shared__ int pfx2[257];
    __shared__ uint32_t skey[4];                // ks0, ks1, sub0, sub1
    int b = blockIdx.x;
    int p = threadIdx.x;
    if (p == 0) {
        uint2 kp  = tf2x32(0u, 42u, 0u, 0u);      // split(key(42),3)[0]
        uint2 ks  = tf2x32(0u, 42u, 0u, 1u);      // split(key(42),3)[1]
        skey[0] = ks.x;  skey[1] = ks.y;
        if (b == 0) {
            uint2 sub = tf2x32(kp.x, kp.y, 0u, 1u);  // _shuffle's subkey
            skey[2] = sub.x; skey[3] = sub.y;
            uint2 kr = tf2x32(0u, 42u, 0u, 2u);      // split(key(42),3)[2]
            g_kr0 = kr.x; g_kr1 = kr.y;
        }
    }
    if (p < 257) hist[p] = 0;
    if (p < 256) hist2[p] = 0;
    __syncthreads();

    // ---- Part A: row-score key + bucket (hash only if valid) ----
    int sl = seq_len[b];
    int nv = sl >> 3;  // seq_len // PATCH
    bool valid = (p < nv);
    uint32_t keyhi = 0x00800000u;              // +inf sentinel > any mantissa
    if (valid)
        // uniform(ks,(B,P)) ordering == ordering of 23-bit mantissa (bits>>9)
        keyhi = rbits32(skey[0], skey[1], (uint32_t)(b * PP + p)) >> 9;
    unsigned long long key = ((unsigned long long)keyhi << 32) | (unsigned)p;
    int bucket = valid ? (int)(keyhi >> 15) : 256;   // 0..255 valid, 256 invalid
    int ofs = atomicAdd(&hist[bucket], 1);

    // ---- Part B (block 0): perm keys + histogram, 2 elems/thread ----
    unsigned long long pk[2];
    int pbkt[2], pofs[2];
    if (b == 0) {
        uint32_t s0 = skey[2], s1 = skey[3];
#pragma unroll
        for (int rr = 0; rr < 2; rr++) {
            int j = p + (rr << 9);
            uint32_t bits = rbits32(s0, s1, (uint32_t)j);
            pk[rr]   = ((unsigned long long)bits << 10) | (unsigned)j;
            pbkt[rr] = (int)(bits >> 24);
            pofs[rr] = atomicAdd(&hist2[pbkt[rr]], 1);
        }
    }
    __syncthreads();

    // ---- exclusive scans: warp 0 -> pfx (row), warp 1 -> pfx2 (perm) ----
    if (p < 32) {
        int base = p * 9;                     // 32*9 = 288 >= 258
        int loc[9];
        int s = 0;
#pragma unroll
        for (int i = 0; i < 9; i++) {
            int idx = base + i;
            int v = (idx < 257) ? hist[idx] : 0;
            loc[i] = s; s += v;
        }
        int t = s;
#pragma unroll
        for (int o = 1; o < 32; o <<= 1) {
            int u = __shfl_up_sync(0xffffffffu, t, o);
            if (p >= o) t += u;
        }
        int excl = t - s;
#pragma unroll
        for (int i = 0; i < 9; i++) {
            int idx = base + i;
            if (idx < 258) pfx[idx] = excl + loc[i];
        }
    } else if (b == 0 && p < 64) {
        int lane = p - 32;
        int base = lane * 8;                  // 32*8 = 256
        int loc[8];
        int s = 0;
#pragma unroll
        for (int i = 0; i < 8; i++) { loc[i] = s; s += hist2[base + i]; }
        int t = s;
#pragma unroll
        for (int o = 1; o < 32; o <<= 1) {
            int u = __shfl_up_sync(0xffffffffu, t, o);
            if (lane >= o) t += u;
        }
        int excl = t - s;
#pragma unroll
        for (int i = 0; i < 8; i++) pfx2[base + i] = excl + loc[i];
        if (lane == 31) pfx2[256] = t;
    }
    __syncthreads();

    // ---- scatter keys into bucket-grouped order ----
    int start = pfx[bucket];
    skeys[start + ofs] = key;
    if (b == 0) {
#pragma unroll
        for (int rr = 0; rr < 2; rr++)
            pkeys[pfx2[pbkt[rr]] + pofs[rr]] = pk[rr];
    }
    __syncthreads();

    // ---- Part A: exact rank = prefix + within-bucket smaller count ----
    int r;
    if (valid) {
        int end = pfx[bucket + 1];
        r = start;
        for (int j = start; j < end; j++) r += (skeys[j] < key);
    } else {
        r = start;   // start = n_valid >= n_corr -> never selected
    }
    // n_corr = floor(0.15f * float(seq_len) / 8.0f), f32 rounding as in JAX
    int nc = (int)floorf(0.15f * (float)sl / 8.0f);
    g_sel[b * PP + p] = (r < nc) ? 1 : 0;
    if (r < nc)              I_out[b * MAXC + r] = (float)p;   // I[b][rank]=patch
    if (p >= nc && p < MAXC) I_out[b * MAXC + p] = -1.0f;      // pad slots

    // ---- Part B (block 0): perm rank -> mask_type ----
    if (b == 0) {
#pragma unroll
        for (int rr = 0; rr < 2; rr++) {
            int j = p + (rr << 9);
            int s2 = pfx2[pbkt[rr]], e2 = pfx2[pbkt[rr] + 1];
            int rank = s2;
            for (int q = s2; q < e2; q++) rank += (pkeys[q] < pk[rr]);
            int grp = (rank < NM) ? 0 : ((rank < NMR) ? 1 : 2);
            mt_out[j] = (float)grp;
            if (j == 0) g_mode = grp;
        }
    }
}

// ---------------------------------------------------------------------------
// Main output pass: 4 independent float4 slots per thread (MLP=4), plain
// cached loads/stores. At the B300 practical HBM ceiling — do not touch.
// Each j-iteration is warp-uniform in sel (one warp spans one patch, K=128).
// ---------------------------------------------------------------------------
__global__ void k_main(const float* __restrict__ x, const float* __restrict__ pos,
                       const float* __restrict__ wm, float* __restrict__ out) {
    int base = (blockIdx.x << 10) + threadIdx.x;   // 1024 float4 per block
    int mode = g_mode;
    unsigned char sv[4];
#pragma unroll
    for (int j = 0; j < 4; j++)
        sv[j] = g_sel[(base + (j << 8)) >> 5];     // (t<<2)>>7 == t>>5
#pragma unroll
    for (int j = 0; j < 4; j++) {
        int t = base + (j << 8);
        int e = t << 2;                            // element index < 2^27
        float4 o;
        if (!sv[j] || mode == 2) {
            o = ((const float4*)x)[t];
        } else {
            float4 po = *(const float4*)(pos + (e & 65535));  // pos[p*K+k], L2-hot
            if (mode == 0) {
                float4 w = *(const float4*)(wm + (e & 127));
                o = make_float4(w.x + po.x, w.y + po.y, w.z + po.z, w.w + po.w);
            } else {
                uint32_t kr0 = g_kr0, kr1 = g_kr1;
                float u[4];
#pragma unroll
                for (int q = 0; q < 4; q++) {
                    uint32_t bits = rbits32(kr0, kr1, (uint32_t)(e + q));
                    u[q] = __uint_as_float((bits >> 9) | 0x3f800000u) - 1.0f;
                }
                o = make_float4(u[0] + po.x, u[1] + po.y, u[2] + po.z, u[3] + po.w);
            }
        }
        ((float4*)out)[t] = o;
    }
}

// ---------------------------------------------------------------------------
extern "C" void kernel_launch(void* const* d_in, const int* in_sizes, int n_in,
                              void* d_out, int out_size) {
    const float* x   = (const float*)d_in[0];
    const float* pos = (const float*)d_in[1];
    const float* wm  = (const float*)d_in[2];
    const int* sl    = (const int*)d_in[3];
    float* out = (float*)d_out;

    k_setup<<<BB, PP>>>(sl, out + I_OFF, out + MT_OFF);
    k_main<<<NTOT / 4 / 1024, 256>>>(x, pos, wm, out);
}